// round 1
// baseline (speedup 1.0000x reference)
#include <cuda_runtime.h>

#define BB 16
#define NNODE 512
#define DD 12
#define HIDN 32
#define NHEAD 4
#define CDIM 8

typedef unsigned long long ull;

// ---------------- scratch (no allocs allowed) ----------------
__device__ __align__(16) float g_buf [BB*NNODE*HIDN];
__device__ __align__(16) float as_buf[BB*NNODE*NHEAD];
__device__ __align__(16) float ad_buf[BB*NNODE*NHEAD];
__device__ __align__(16) float ti_buf[BB*NNODE*HIDN];  // ti + b1 folded
__device__ __align__(16) float tj_buf[BB*NNODE*HIDN];

// ---------------- f32x2 helpers (Blackwell packed fp32) ----------------
__device__ __forceinline__ ull add2(ull a, ull b){ ull r; asm("add.rn.f32x2 %0, %1, %2;" : "=l"(r) : "l"(a), "l"(b)); return r; }
__device__ __forceinline__ ull fma2(ull a, ull b, ull c){ ull r; asm("fma.rn.f32x2 %0, %1, %2, %3;" : "=l"(r) : "l"(a), "l"(b), "l"(c)); return r; }
__device__ __forceinline__ ull pack2(float x, float y){
    ull r; asm("mov.b64 %0, {%1, %2};" : "=l"(r) : "r"(__float_as_uint(x)), "r"(__float_as_uint(y))); return r;
}
__device__ __forceinline__ float2 unpack2(ull v){
    unsigned lo, hi; asm("mov.b64 {%0, %1}, %2;" : "=r"(lo), "=r"(hi) : "l"(v));
    return make_float2(__uint_as_float(lo), __uint_as_float(hi));
}

// ================= K1: per-node embeddings h -> g, a_s, a_d =================
__global__ void __launch_bounds__(256) k1_embed(
    const float* __restrict__ x, const float* __restrict__ Wp, const float* __restrict__ bp,
    const float* __restrict__ Wg, const float* __restrict__ att_src, const float* __restrict__ att_dst)
{
    __shared__ float Wp_s[HIDN*DD];
    __shared__ float bp_s[HIDN];
    __shared__ float Wg_s[HIDN*HIDN];
    __shared__ float asr_s[HIDN], adr_s[HIDN];
    int t = threadIdx.x;
    for (int i = t; i < HIDN*DD; i += 256) Wp_s[i] = Wp[i];
    for (int i = t; i < HIDN*HIDN; i += 256) Wg_s[i] = Wg[i];
    if (t < HIDN) { bp_s[t] = bp[t]; asr_s[t] = att_src[t]; adr_s[t] = att_dst[t]; }
    __syncthreads();

    int node = blockIdx.x * 256 + t;
    if (node >= BB*NNODE) return;

    float xv[DD];
#pragma unroll
    for (int d = 0; d < DD; ++d) xv[d] = x[node*DD + d];

    float h[HIDN];
#pragma unroll
    for (int k = 0; k < HIDN; ++k) {
        float acc = bp_s[k];
#pragma unroll
        for (int d = 0; d < DD; ++d) acc = fmaf(xv[d], Wp_s[k*DD + d], acc);
        h[k] = fmaxf(acc, 0.f);
    }

    float asum[NHEAD] = {0,0,0,0}, adsum[NHEAD] = {0,0,0,0};
    float4 gq;
#pragma unroll
    for (int k = 0; k < HIDN; ++k) {
        float acc = 0.f;
#pragma unroll
        for (int d = 0; d < HIDN; ++d) acc = fmaf(h[d], Wg_s[k*HIDN + d], acc);
        asum[k >> 3]  = fmaf(acc, asr_s[k], asum[k >> 3]);
        adsum[k >> 3] = fmaf(acc, adr_s[k], adsum[k >> 3]);
        ((float*)&gq)[k & 3] = acc;
        if ((k & 3) == 3) ((float4*)g_buf)[(node*HIDN + k - 3) >> 2] = gq;
    }
    ((float4*)as_buf)[node] = make_float4(asum[0], asum[1], asum[2], asum[3]);
    ((float4*)ad_buf)[node] = make_float4(adsum[0], adsum[1], adsum[2], adsum[3]);
}

// ================= K2: attention softmax (over i) + h_gnn + ti/tj =================
// Grid (16 j-tiles, 16 batches), 256 threads.
// SMEM: g (padded float2), a_s transposed, adj mask bits, partials, h_gnn.
// Warp w: jhalf = w&1 (16 j's), iq = w>>2? -> iq = w>>1 (128 i's each).
// Lane: h = lane&3, jslot = lane>>2; each lane handles 2 adjacent j's.
#define SM_G     0
#define SM_AST   (512*17*8)              // 69632
#define SM_MASK  (SM_AST + 4*520*4)      // 77952
#define SM_PART  (SM_MASK + 512*4)       // 80000
#define SM_HG    (SM_PART + 4*32*4*9*4)  // 98432
#define SM_TOTAL (SM_HG + 32*33*4)       // 102656

__global__ void __launch_bounds__(256) k2_attn(
    const int* __restrict__ adj, const float* __restrict__ bias_g,
    const float* __restrict__ W1, const float* __restrict__ b1)
{
    extern __shared__ char sm[];
    float2*   g2_s   = (float2*)(sm + SM_G);
    float*    asT_s  = (float*) (sm + SM_AST);
    unsigned* mask_s = (unsigned*)(sm + SM_MASK);
    float*    part_s = (float*) (sm + SM_PART);
    float*    hg_s   = (float*) (sm + SM_HG);

    int t  = threadIdx.x;
    int b  = blockIdx.y;
    int j0 = blockIdx.x * 32;

    // load g[b] into padded smem (row = 17 float2)
    const float2* gp = (const float2*)g_buf + (size_t)b * NNODE * (HIDN/2);
    for (int idx = t; idx < NNODE*(HIDN/2); idx += 256) {
        int i = idx >> 4, p = idx & 15;
        g2_s[i*17 + p] = gp[idx];
    }
    // a_s transposed: asT_s[h][i], row stride 520 (conflict-free)
    const float* asp = as_buf + (size_t)b * NNODE * NHEAD;
    for (int idx = t; idx < NNODE*NHEAD; idx += 256) {
        int i = idx >> 2, h = idx & 3;
        asT_s[h*520 + i] = asp[idx];
    }
    // adjacency column bits (adj | eye), 32 j's per block
    for (int ii = t; ii < NNODE; ii += 256) {
        const int4* arow = (const int4*)(adj + ((size_t)(b*NNODE + ii))*NNODE + j0);
        unsigned bits = 0;
#pragma unroll
        for (int q = 0; q < 8; ++q) {
            int4 v = arow[q];
            bits |= (v.x ? 1u : 0u) << (4*q);
            bits |= (v.y ? 1u : 0u) << (4*q+1);
            bits |= (v.z ? 1u : 0u) << (4*q+2);
            bits |= (v.w ? 1u : 0u) << (4*q+3);
        }
        unsigned d = (unsigned)(ii - j0);
        if (d < 32u) bits |= (1u << d);
        mask_s[ii] = bits;
    }
    __syncthreads();

    int w = t >> 5, lane = t & 31;
    int h = lane & 3, jslot = lane >> 2;
    int jhalf = w & 1, iq = w >> 1;
    int jl0 = jhalf*16 + jslot*2, jl1 = jl0 + 1;

    float ad0 = ad_buf[((size_t)(b*NNODE) + j0 + jl0)*NHEAD + h];
    float ad1 = ad_buf[((size_t)(b*NNODE) + j0 + jl1)*NHEAD + h];
    float den0 = 0.f, den1 = 0.f;
    ull num0[4] = {0,0,0,0}, num1[4] = {0,0,0,0};
    const ull* gvp = (const ull*)g2_s;

    int ibeg = iq * 128, iend = ibeg + 128;
#pragma unroll 2
    for (int i = ibeg; i < iend; ++i) {
        float asv   = asT_s[h*520 + i];
        unsigned mw = mask_s[i];
        ull gv0 = gvp[i*17 + h*4 + 0];
        ull gv1 = gvp[i*17 + h*4 + 1];
        ull gv2 = gvp[i*17 + h*4 + 2];
        ull gv3 = gvp[i*17 + h*4 + 3];
        {
            float s = asv + ad0;
            s = fmaxf(s, 0.2f*s);               // leaky_relu(0.2)
            float e = __expf(s);                // logits tiny -> no max needed
            e = ((mw >> jl0) & 1u) ? e : 0.f;   // masked => exact 0
            den0 += e;
            ull e2 = pack2(e, e);
            num0[0] = fma2(e2, gv0, num0[0]);
            num0[1] = fma2(e2, gv1, num0[1]);
            num0[2] = fma2(e2, gv2, num0[2]);
            num0[3] = fma2(e2, gv3, num0[3]);
        }
        {
            float s = asv + ad1;
            s = fmaxf(s, 0.2f*s);
            float e = __expf(s);
            e = ((mw >> jl1) & 1u) ? e : 0.f;
            den1 += e;
            ull e2 = pack2(e, e);
            num1[0] = fma2(e2, gv0, num1[0]);
            num1[1] = fma2(e2, gv1, num1[1]);
            num1[2] = fma2(e2, gv2, num1[2]);
            num1[3] = fma2(e2, gv3, num1[3]);
        }
    }
    // write per-iq partials
    {
        float* pp = part_s + ((iq*32 + jl0)*4 + h)*9;
        pp[0] = den0;
#pragma unroll
        for (int c = 0; c < 4; ++c) { float2 f = unpack2(num0[c]); pp[1+2*c] = f.x; pp[2+2*c] = f.y; }
        pp = part_s + ((iq*32 + jl1)*4 + h)*9;
        pp[0] = den1;
#pragma unroll
        for (int c = 0; c < 4; ++c) { float2 f = unpack2(num1[c]); pp[1+2*c] = f.x; pp[2+2*c] = f.y; }
    }
    __syncthreads();

    // reduce 4 i-quarters -> h_gnn[j][32] (+bias_g)
    if (t < 128) {
        int jl = t >> 2, hh = t & 3;
        float den = 0.f, nm[8] = {0,0,0,0,0,0,0,0};
#pragma unroll
        for (int q = 0; q < 4; ++q) {
            const float* pp = part_s + ((q*32 + jl)*4 + hh)*9;
            den += pp[0];
#pragma unroll
            for (int c = 0; c < 8; ++c) nm[c] += pp[1+c];
        }
        float inv = __fdividef(1.f, den);   // diag always unmasked => den > 0
#pragma unroll
        for (int c = 0; c < 8; ++c)
            hg_s[jl*33 + hh*8 + c] = fmaf(nm[c], inv, bias_g[hh*8 + c]);
    }
    __syncthreads();

    // ti' = h_gnn @ W1[:, :32]^T + b1 ; tj = h_gnn @ W1[:, 32:]^T
    for (int k = t; k < 32*64; k += 256) {
        int j = k >> 6, o = k & 63;
        const float* wrow = (o < 32) ? (W1 + o*64) : (W1 + (o-32)*64 + 32);
        float acc = (o < 32) ? b1[o] : 0.f;
#pragma unroll
        for (int d = 0; d < 32; ++d) acc = fmaf(hg_s[j*33 + d], wrow[d], acc);
        size_t node = (size_t)(b*NNODE) + j0 + j;
        if (o < 32) ti_buf[node*32 + o] = acc;
        else        tj_buf[node*32 + (o-32)] = acc;
    }
}

// ================= K4: pairwise edge scorer (dominant) =================
// Grid (4 j-tiles x 16 i-tiles x 16 b), 256 threads.
// Block covers 32 i (lanes) x 128 j; warp w owns j-chunk of 16.
// Inner math fully f32x2-packed over h-pairs; relu halves on ALU pipe.
__global__ void __launch_bounds__(256) k4_score(
    const int* __restrict__ adj, const float* __restrict__ w2,
    const float* __restrict__ b2, float* __restrict__ out)
{
    __shared__ ull tj2_s[128*16];
    __shared__ ull w2p_s[16];
    int t = threadIdx.x;
    int b  = blockIdx.z;
    int i0 = blockIdx.y * 32;
    int j0 = blockIdx.x * 128;

    const ull* tjp = (const ull*)tj_buf + ((size_t)(b*NNODE) + j0)*16;
    for (int idx = t; idx < 128*16; idx += 256) tj2_s[idx] = tjp[idx];
    if (t < 16) w2p_s[t] = pack2(w2[2*t], w2[2*t+1]);
    __syncthreads();

    int w = t >> 5, lane = t & 31;
    int i  = i0 + lane;
    int jw = w * 16;

    ull ti2[16];
    const ull* tip = (const ull*)ti_buf + ((size_t)(b*NNODE) + i)*16;
#pragma unroll
    for (int p = 0; p < 16; ++p) ti2[p] = tip[p];

    ull acc2[16];
#pragma unroll
    for (int jj = 0; jj < 16; ++jj) acc2[jj] = 0ull;

#pragma unroll
    for (int hp = 0; hp < 16; ++hp) {
        ull w2v = w2p_s[hp];
        ull tiv = ti2[hp];
#pragma unroll
        for (int jj = 0; jj < 16; ++jj) {
            ull v = add2(tiv, tj2_s[(jw + jj)*16 + hp]);   // LDS broadcast
            float2 vf = unpack2(v);
            vf.x = fmaxf(vf.x, 0.f);
            vf.y = fmaxf(vf.y, 0.f);
            acc2[jj] = fma2(w2v, pack2(vf.x, vf.y), acc2[jj]);
        }
    }

    float b2v = b2[0];
    float sc[16];
#pragma unroll
    for (int jj = 0; jj < 16; ++jj) {
        float2 a = unpack2(acc2[jj]);
        float logit = a.x + a.y + b2v;
        sc[jj] = __fdividef(1.f, 1.f + __expf(-logit));    // sigmoid
    }

    const int4* ap = (const int4*)(adj + ((size_t)(b*NNODE) + i)*NNODE + j0 + jw);
    float4*     op = (float4*)    (out + ((size_t)(b*NNODE) + i)*NNODE + j0 + jw);
    int jg = j0 + jw;
#pragma unroll
    for (int q = 0; q < 4; ++q) {
        int4 av = ap[q];
        float4 o;
        o.x = (av.x != 0 && i != jg + 4*q + 0) ? sc[4*q+0] : 0.f;
        o.y = (av.y != 0 && i != jg + 4*q + 1) ? sc[4*q+1] : 0.f;
        o.z = (av.z != 0 && i != jg + 4*q + 2) ? sc[4*q+2] : 0.f;
        o.w = (av.w != 0 && i != jg + 4*q + 3) ? sc[4*q+3] : 0.f;
        op[q] = o;
    }
}

// ================= launch =================
extern "C" void kernel_launch(void* const* d_in, const int* in_sizes, int n_in,
                              void* d_out, int out_size)
{
    const float* x        = (const float*)d_in[0];
    const int*   adj      = (const int*)  d_in[1];
    const float* Wp       = (const float*)d_in[2];
    const float* bp       = (const float*)d_in[3];
    const float* Wg       = (const float*)d_in[4];
    const float* att_src  = (const float*)d_in[5];
    const float* att_dst  = (const float*)d_in[6];
    const float* bias_g   = (const float*)d_in[7];
    const float* W1       = (const float*)d_in[8];
    const float* b1       = (const float*)d_in[9];
    const float* w2       = (const float*)d_in[10];
    const float* b2       = (const float*)d_in[11];
    float* out = (float*)d_out;

    k1_embed<<<BB*NNODE/256, 256>>>(x, Wp, bp, Wg, att_src, att_dst);

    cudaFuncSetAttribute(k2_attn, cudaFuncAttributeMaxDynamicSharedMemorySize, SM_TOTAL);
    k2_attn<<<dim3(NNODE/32, BB), 256, SM_TOTAL>>>(adj, bias_g, W1, b1);

    k4_score<<<dim3(NNODE/128, NNODE/32, BB), 256>>>(adj, w2, b2, out);
}

// round 2
// speedup vs baseline: 1.0563x; 1.0563x over previous
#include <cuda_runtime.h>

#define BB 16
#define NNODE 512
#define DD 12
#define HIDN 32
#define NHEAD 4
#define CDIM 8

typedef unsigned long long ull;

// ---------------- scratch (no allocs allowed) ----------------
__device__ __align__(16) float g_buf  [BB*NNODE*HIDN];
__device__ __align__(16) float as_buf [BB*NNODE*NHEAD];
__device__ __align__(16) float ad_buf [BB*NNODE*NHEAD];
__device__ __align__(16) float ti_buf [BB*NNODE*HIDN];   // ti + b1 folded, row-major [node][32]
__device__ __align__(16) float tjT_buf[BB*HIDN*NNODE];   // transposed: [(b*16+p)*512 + j] ull pairs

// ---------------- f32x2 helpers (Blackwell packed fp32) ----------------
__device__ __forceinline__ ull add2(ull a, ull b){ ull r; asm("add.rn.f32x2 %0, %1, %2;" : "=l"(r) : "l"(a), "l"(b)); return r; }
__device__ __forceinline__ ull fma2(ull a, ull b, ull c){ ull r; asm("fma.rn.f32x2 %0, %1, %2, %3;" : "=l"(r) : "l"(a), "l"(b), "l"(c)); return r; }
__device__ __forceinline__ ull pack2(float x, float y){
    ull r; asm("mov.b64 %0, {%1, %2};" : "=l"(r) : "r"(__float_as_uint(x)), "r"(__float_as_uint(y))); return r;
}
__device__ __forceinline__ float2 unpack2(ull v){
    unsigned lo, hi; asm("mov.b64 {%0, %1}, %2;" : "=r"(lo), "=r"(hi) : "l"(v));
    return make_float2(__uint_as_float(lo), __uint_as_float(hi));
}

// ================= K1: per-node embeddings h -> g, a_s, a_d =================
// 128 blocks x 256 threads; block = 64 nodes; thread = (node, k-octet).
__global__ void __launch_bounds__(256) k1_embed(
    const float* __restrict__ x, const float* __restrict__ Wp, const float* __restrict__ bp,
    const float* __restrict__ Wg, const float* __restrict__ att_src, const float* __restrict__ att_dst)
{
    __shared__ float xs[64*12];
    __shared__ float Wp_s[HIDN*DD];
    __shared__ float bp_s[HIDN];
    __shared__ float Wg_s[HIDN*HIDN];
    __shared__ float asr_s[HIDN], adr_s[HIDN];
    __shared__ float hs[64*33];

    int t  = threadIdx.x;
    int nb = blockIdx.x * 64;

    for (int i = t; i < 64*12; i += 256) xs[i] = x[(size_t)nb*12 + i];
    for (int i = t; i < HIDN*DD; i += 256) Wp_s[i] = Wp[i];
    for (int i = t; i < HIDN*HIDN; i += 256) Wg_s[i] = Wg[i];
    if (t < HIDN) { bp_s[t] = bp[t]; asr_s[t] = att_src[t]; adr_s[t] = att_dst[t]; }
    __syncthreads();

    int n = t & 63, kg = t >> 6;   // kg = k-octet = head index

    // stage 1: h[n][kg*8 .. kg*8+7]
    float xv[DD];
#pragma unroll
    for (int d = 0; d < DD; ++d) xv[d] = xs[n*DD + d];
#pragma unroll
    for (int kk = 0; kk < 8; ++kk) {
        int k = kg*8 + kk;
        float acc = bp_s[k];
#pragma unroll
        for (int d = 0; d < DD; ++d) acc = fmaf(xv[d], Wp_s[k*DD + d], acc);
        hs[n*33 + k] = fmaxf(acc, 0.f);
    }
    __syncthreads();

    // stage 2: g[n][kg*8..+8], a_s/a_d for head kg
    float hv[HIDN];
#pragma unroll
    for (int d = 0; d < HIDN; ++d) hv[d] = hs[n*33 + d];

    float gv[8];
    float asum = 0.f, adsum = 0.f;
#pragma unroll
    for (int c = 0; c < 8; ++c) {
        int k = kg*8 + c;
        float acc = 0.f;
#pragma unroll
        for (int d = 0; d < HIDN; ++d) acc = fmaf(hv[d], Wg_s[k*HIDN + d], acc);
        gv[c] = acc;
        asum  = fmaf(acc, asr_s[k], asum);
        adsum = fmaf(acc, adr_s[k], adsum);
    }
    int node = nb + n;
    float4* gp = (float4*)(g_buf + (size_t)node*HIDN + kg*8);
    gp[0] = make_float4(gv[0], gv[1], gv[2], gv[3]);
    gp[1] = make_float4(gv[4], gv[5], gv[6], gv[7]);
    as_buf[node*NHEAD + kg] = asum;
    ad_buf[node*NHEAD + kg] = adsum;
}

// ================= K2: attention softmax (over i) + h_gnn + ti/tjT =================
// Grid (16 j-tiles, 16 batches), 256 threads. g padded to 18 float2/row (144B, 16B-aligned).
#define SM_G     0
#define SM_AST   (512*18*8)              // 73728
#define SM_MASK  (SM_AST + 4*520*4)      // 82048
#define SM_PART  (SM_MASK + 512*4)       // 84096
#define SM_HG    (SM_PART + 4*32*4*9*4)  // 102528
#define SM_TOTAL (SM_HG + 32*33*4)       // 106752

__global__ void __launch_bounds__(256) k2_attn(
    const int* __restrict__ adj, const float* __restrict__ bias_g,
    const float* __restrict__ W1, const float* __restrict__ b1)
{
    extern __shared__ char sm[];
    float2*   g2_s   = (float2*)(sm + SM_G);
    float*    asT_s  = (float*) (sm + SM_AST);
    unsigned* mask_s = (unsigned*)(sm + SM_MASK);
    float*    part_s = (float*) (sm + SM_PART);
    float*    hg_s   = (float*) (sm + SM_HG);

    int t  = threadIdx.x;
    int b  = blockIdx.y;
    int j0 = blockIdx.x * 32;
    int w = t >> 5, lane = t & 31;

    // load g[b] into padded smem (row = 18 float2 = 144B)
    const float2* gp = (const float2*)g_buf + (size_t)b * NNODE * (HIDN/2);
    for (int idx = t; idx < NNODE*(HIDN/2); idx += 256) {
        int i = idx >> 4, p = idx & 15;
        g2_s[i*18 + p] = gp[idx];
    }
    // a_s transposed: asT_s[h][i], row stride 520
    const float* asp = as_buf + (size_t)b * NNODE * NHEAD;
    for (int idx = t; idx < NNODE*NHEAD; idx += 256) {
        int i = idx >> 2, h = idx & 3;
        asT_s[h*520 + i] = asp[idx];
    }
    // adjacency column bits (adj | eye): coalesced row read + ballot
    {
        const int* ab = adj + (size_t)b * NNODE * NNODE + j0;
        for (int i = w; i < NNODE; i += 8) {
            int a = ab[(size_t)i * NNODE + lane];
            unsigned bits = __ballot_sync(0xffffffffu, (a != 0) || (i == j0 + lane));
            if (lane == 0) mask_s[i] = bits;
        }
    }
    __syncthreads();

    int h = lane & 3, jslot = lane >> 2;
    int jhalf = w & 1, iq = w >> 1;
    int jl0 = jhalf*16 + jslot*2, jl1 = jl0 + 1;

    float ad0 = ad_buf[((size_t)(b*NNODE) + j0 + jl0)*NHEAD + h];
    float ad1 = ad_buf[((size_t)(b*NNODE) + j0 + jl1)*NHEAD + h];
    float den0 = 0.f, den1 = 0.f;
    ull num0[4] = {0,0,0,0}, num1[4] = {0,0,0,0};
    const ulonglong2* gq2 = (const ulonglong2*)g2_s;   // row = 9 ull2

    int ibeg = iq * 128, iend = ibeg + 128;
#pragma unroll 2
    for (int i = ibeg; i < iend; ++i) {
        float asv   = asT_s[h*520 + i];
        unsigned mw = mask_s[i];
        ulonglong2 ga = gq2[i*9 + h*2];       // LDS.128
        ulonglong2 gb = gq2[i*9 + h*2 + 1];   // LDS.128
        {
            float s = asv + ad0;
            s = fmaxf(s, 0.2f*s);               // leaky_relu(0.2)
            float e = __expf(s);                // logits tiny -> no max-sub needed
            e = ((mw >> jl0) & 1u) ? e : 0.f;
            den0 += e;
            ull e2 = pack2(e, e);
            num0[0] = fma2(e2, ga.x, num0[0]);
            num0[1] = fma2(e2, ga.y, num0[1]);
            num0[2] = fma2(e2, gb.x, num0[2]);
            num0[3] = fma2(e2, gb.y, num0[3]);
        }
        {
            float s = asv + ad1;
            s = fmaxf(s, 0.2f*s);
            float e = __expf(s);
            e = ((mw >> jl1) & 1u) ? e : 0.f;
            den1 += e;
            ull e2 = pack2(e, e);
            num1[0] = fma2(e2, ga.x, num1[0]);
            num1[1] = fma2(e2, ga.y, num1[1]);
            num1[2] = fma2(e2, gb.x, num1[2]);
            num1[3] = fma2(e2, gb.y, num1[3]);
        }
    }
    // write per-iq partials
    {
        float* pp = part_s + ((iq*32 + jl0)*4 + h)*9;
        pp[0] = den0;
#pragma unroll
        for (int c = 0; c < 4; ++c) { float2 f = unpack2(num0[c]); pp[1+2*c] = f.x; pp[2+2*c] = f.y; }
        pp = part_s + ((iq*32 + jl1)*4 + h)*9;
        pp[0] = den1;
#pragma unroll
        for (int c = 0; c < 4; ++c) { float2 f = unpack2(num1[c]); pp[1+2*c] = f.x; pp[2+2*c] = f.y; }
    }
    __syncthreads();

    // reduce 4 i-quarters -> h_gnn[j][32] (+bias_g)
    if (t < 128) {
        int jl = t >> 2, hh = t & 3;
        float den = 0.f, nm[8] = {0,0,0,0,0,0,0,0};
#pragma unroll
        for (int q = 0; q < 4; ++q) {
            const float* pp = part_s + ((q*32 + jl)*4 + hh)*9;
            den += pp[0];
#pragma unroll
            for (int c = 0; c < 8; ++c) nm[c] += pp[1+c];
        }
        float inv = __fdividef(1.f, den);   // diag always unmasked => den > 0
#pragma unroll
        for (int c = 0; c < 8; ++c)
            hg_s[jl*33 + hh*8 + c] = fmaf(nm[c], inv, bias_g[hh*8 + c]);
    }
    __syncthreads();

    // ti' = h_gnn @ W1[:, :32]^T + b1 (row-major); tj = h_gnn @ W1[:, 32:]^T (transposed layout)
    for (int k = t; k < 32*64; k += 256) {
        int j = k >> 6, o = k & 63;
        const float* wrow = (o < 32) ? (W1 + o*64) : (W1 + (o-32)*64 + 32);
        float acc = (o < 32) ? b1[o] : 0.f;
#pragma unroll
        for (int d = 0; d < 32; ++d) acc = fmaf(hg_s[j*33 + d], wrow[d], acc);
        if (o < 32) {
            ti_buf[((size_t)(b*NNODE) + j0 + j)*32 + o] = acc;
        } else {
            int oo = o - 32;
            tjT_buf[(((size_t)b*16 + (oo>>1))*NNODE + j0 + j)*2 + (oo & 1)] = acc;
        }
    }
}

// ================= K4: pairwise edge scorer (dominant) =================
// lane = j (coalesced adj/out/tjT); ti broadcast from smem tile.
// Grid (2 j-halves x 16 i-tiles x 16 b), 256 threads; warp owns 32 j, loops 32 i.
#define K4_IT 32
__global__ void __launch_bounds__(256) k4_score(
    const int* __restrict__ adj, const float* __restrict__ w2,
    const float* __restrict__ b2, float* __restrict__ out)
{
    __shared__ ull ti_s[K4_IT*16];
    __shared__ ull w2p_s[16];
    int t = threadIdx.x, lane = t & 31, w = t >> 5;
    int b  = blockIdx.z;
    int i0 = blockIdx.y * K4_IT;
    int j  = blockIdx.x * 256 + w*32 + lane;

    const ull* tiu = (const ull*)ti_buf + ((size_t)(b*NNODE) + i0)*16;
    for (int idx = t; idx < K4_IT*16; idx += 256) ti_s[idx] = tiu[idx];
    if (t < 16) w2p_s[t] = pack2(w2[2*t], w2[2*t+1]);
    __syncthreads();

    // per-lane tj (coalesced from transposed buffer) and w2 in registers
    ull tj2[16], w2r[16];
    const ull* tjp = (const ull*)tjT_buf;
#pragma unroll
    for (int p = 0; p < 16; ++p) tj2[p] = tjp[((size_t)b*16 + p)*NNODE + j];
#pragma unroll
    for (int p = 0; p < 16; ++p) w2r[p] = w2p_s[p];

    float b2v = b2[0];
    const int* arow = adj + ((size_t)(b*NNODE) + i0)*NNODE + j;
    float*     orow = out + ((size_t)(b*NNODE) + i0)*NNODE + j;

    for (int i = 0; i < K4_IT; ++i) {
        const ulonglong2* tp = (const ulonglong2*)&ti_s[i*16];
        ull a0 = 0, a1 = 0, a2 = 0, a3 = 0;
#pragma unroll
        for (int q = 0; q < 8; ++q) {
            ulonglong2 tv = tp[q];                 // LDS.128 broadcast
            ull v0 = add2(tj2[2*q],   tv.x);
            ull v1 = add2(tj2[2*q+1], tv.y);
            float2 f0 = unpack2(v0), f1 = unpack2(v1);
            f0.x = fmaxf(f0.x, 0.f); f0.y = fmaxf(f0.y, 0.f);
            f1.x = fmaxf(f1.x, 0.f); f1.y = fmaxf(f1.y, 0.f);
            if (q & 1) {
                a2 = fma2(w2r[2*q],   pack2(f0.x, f0.y), a2);
                a3 = fma2(w2r[2*q+1], pack2(f1.x, f1.y), a3);
            } else {
                a0 = fma2(w2r[2*q],   pack2(f0.x, f0.y), a0);
                a1 = fma2(w2r[2*q+1], pack2(f1.x, f1.y), a1);
            }
        }
        float2 s0 = unpack2(a0), s1 = unpack2(a1), s2 = unpack2(a2), s3 = unpack2(a3);
        float logit = ((s0.x + s0.y) + (s1.x + s1.y)) + ((s2.x + s2.y) + (s3.x + s3.y)) + b2v;
        float sc = __fdividef(1.f, 1.f + __expf(-logit));

        int ii = i0 + i;
        int av = arow[(size_t)i * NNODE];          // coalesced (lane = j)
        orow[(size_t)i * NNODE] = (av != 0 && ii != j) ? sc : 0.f;
    }
}

// ================= launch =================
extern "C" void kernel_launch(void* const* d_in, const int* in_sizes, int n_in,
                              void* d_out, int out_size)
{
    const float* x        = (const float*)d_in[0];
    const int*   adj      = (const int*)  d_in[1];
    const float* Wp       = (const float*)d_in[2];
    const float* bp       = (const float*)d_in[3];
    const float* Wg       = (const float*)d_in[4];
    const float* att_src  = (const float*)d_in[5];
    const float* att_dst  = (const float*)d_in[6];
    const float* bias_g   = (const float*)d_in[7];
    const float* W1       = (const float*)d_in[8];
    const float* b1       = (const float*)d_in[9];
    const float* w2       = (const float*)d_in[10];
    const float* b2       = (const float*)d_in[11];
    float* out = (float*)d_out;

    k1_embed<<<BB*NNODE/64, 256>>>(x, Wp, bp, Wg, att_src, att_dst);

    cudaFuncSetAttribute(k2_attn, cudaFuncAttributeMaxDynamicSharedMemorySize, SM_TOTAL);
    k2_attn<<<dim3(NNODE/32, BB), 256, SM_TOTAL>>>(adj, bias_g, W1, b1);

    k4_score<<<dim3(2, NNODE/K4_IT, BB), 256>>>(adj, w2, b2, out);
}

// round 3
// speedup vs baseline: 1.0712x; 1.0140x over previous
#include <cuda_runtime.h>

#define BB 16
#define NNODE 512
#define DD 12
#define HIDN 32
#define NHEAD 4
#define CDIM 8

typedef unsigned long long ull;

// ---------------- scratch (no allocs allowed) ----------------
__device__ __align__(16) float g_buf  [BB*NNODE*HIDN];
__device__ __align__(16) float as_buf [BB*NNODE*NHEAD];
__device__ __align__(16) float ad_buf [BB*NNODE*NHEAD];
__device__ __align__(16) float ti_buf [BB*NNODE*HIDN];   // ti + b1 folded, row-major [node][32]
__device__ __align__(16) float tjT_buf[BB*HIDN*NNODE];   // transposed: [(b*16+p)*512 + j] ull pairs
__device__ __align__(16) float pi_buf [BB*NNODE];        // 0.5 * sum_h w2[h]*ti'[node][h]
__device__ __align__(16) float pj_buf [BB*NNODE];        // 0.5 * sum_h w2[h]*tj [node][h]

// ---------------- f32x2 helpers (Blackwell packed fp32) ----------------
__device__ __forceinline__ ull add2(ull a, ull b){ ull r; asm("add.rn.f32x2 %0, %1, %2;" : "=l"(r) : "l"(a), "l"(b)); return r; }
__device__ __forceinline__ ull fma2(ull a, ull b, ull c){ ull r; asm("fma.rn.f32x2 %0, %1, %2, %3;" : "=l"(r) : "l"(a), "l"(b), "l"(c)); return r; }
__device__ __forceinline__ ull pack2(float x, float y){
    ull r; asm("mov.b64 %0, {%1, %2};" : "=l"(r) : "r"(__float_as_uint(x)), "r"(__float_as_uint(y))); return r;
}
__device__ __forceinline__ float2 unpack2(ull v){
    unsigned lo, hi; asm("mov.b64 {%0, %1}, %2;" : "=r"(lo), "=r"(hi) : "l"(v));
    return make_float2(__uint_as_float(lo), __uint_as_float(hi));
}
__device__ __forceinline__ float ex2f(float x){ float r; asm("ex2.approx.f32 %0, %1;" : "=f"(r) : "f"(x)); return r; }

// ================= K1: per-node embeddings h -> g, a_s, a_d =================
// 128 blocks x 256 threads; thread = (node, k-octet); h computed redundantly (x4)
// to remove the mid-kernel barrier + smem staging (latency-bound at low occ).
__global__ void __launch_bounds__(256) k1_embed(
    const float* __restrict__ x, const float* __restrict__ Wp, const float* __restrict__ bp,
    const float* __restrict__ Wg, const float* __restrict__ att_src, const float* __restrict__ att_dst)
{
    __shared__ float xs[64*12];
    __shared__ float Wp_s[HIDN*DD];
    __shared__ float bp_s[HIDN];
    __shared__ float Wg_s[HIDN*HIDN];
    __shared__ float asr_s[HIDN], adr_s[HIDN];

    int t  = threadIdx.x;
    int nb = blockIdx.x * 64;

    for (int i = t; i < 64*12; i += 256) xs[i] = x[(size_t)nb*12 + i];
    for (int i = t; i < HIDN*DD; i += 256) Wp_s[i] = Wp[i];
    for (int i = t; i < HIDN*HIDN; i += 256) Wg_s[i] = Wg[i];
    if (t < HIDN) { bp_s[t] = bp[t]; asr_s[t] = att_src[t]; adr_s[t] = att_dst[t]; }
    __syncthreads();

    int n = t & 63, kg = t >> 6;   // kg = k-octet = head index

    float xv[DD];
#pragma unroll
    for (int d = 0; d < DD; ++d) xv[d] = xs[n*DD + d];

    float hv[HIDN];
#pragma unroll
    for (int k = 0; k < HIDN; ++k) {
        float acc = bp_s[k];
#pragma unroll
        for (int d = 0; d < DD; ++d) acc = fmaf(xv[d], Wp_s[k*DD + d], acc);
        hv[k] = fmaxf(acc, 0.f);
    }

    float gv[8];
    float asum = 0.f, adsum = 0.f;
#pragma unroll
    for (int c = 0; c < 8; ++c) {
        int k = kg*8 + c;
        float acc = 0.f;
#pragma unroll
        for (int d = 0; d < HIDN; ++d) acc = fmaf(hv[d], Wg_s[k*HIDN + d], acc);
        gv[c] = acc;
        asum  = fmaf(acc, asr_s[k], asum);
        adsum = fmaf(acc, adr_s[k], adsum);
    }
    int node = nb + n;
    float4* gp = (float4*)(g_buf + (size_t)node*HIDN + kg*8);
    gp[0] = make_float4(gv[0], gv[1], gv[2], gv[3]);
    gp[1] = make_float4(gv[4], gv[5], gv[6], gv[7]);
    as_buf[node*NHEAD + kg] = asum;
    ad_buf[node*NHEAD + kg] = adsum;
}

// ================= K2: attention softmax (over i) + h_gnn + ti/tjT + pi/pj =================
// Grid (16 j-tiles, 16 batches), 256 threads.
#define SM_G     0                       // 512*16 float2 = 65536
#define SM_AST   65536                   // 4*520*4 = 8320
#define SM_MASK  73856                   // 512*4 = 2048
#define SM_PART  75904                   // 4*32*4*9*4 = 18432
#define SM_HG    94336                   // 32*33*4 = 4224
#define SM_W2    98560                   // 128
#define SM_TOTAL 98688

__global__ void __launch_bounds__(256) k2_attn(
    const int* __restrict__ adj, const float* __restrict__ bias_g,
    const float* __restrict__ W1, const float* __restrict__ b1,
    const float* __restrict__ w2)
{
    extern __shared__ char sm[];
    float2*   g2_s   = (float2*)(sm + SM_G);
    float*    asT_s  = (float*) (sm + SM_AST);
    unsigned* mask_s = (unsigned*)(sm + SM_MASK);
    float*    part_s = (float*) (sm + SM_PART);
    float*    hg_s   = (float*) (sm + SM_HG);
    float*    w2_s   = (float*) (sm + SM_W2);

    int t  = threadIdx.x;
    int b  = blockIdx.y;
    int j0 = blockIdx.x * 32;
    int w = t >> 5, lane = t & 31;

    // g[b] -> smem (straight float4 copy, 64KB)
    {
        const float4* gp = (const float4*)(g_buf + (size_t)b * NNODE * HIDN);
        float4* gs = (float4*)g2_s;
        for (int idx = t; idx < NNODE*HIDN/4; idx += 256) gs[idx] = gp[idx];
    }
    // a_s transposed: asT_s[h][i], row stride 520
    const float* asp = as_buf + (size_t)b * NNODE * NHEAD;
    for (int idx = t; idx < NNODE*NHEAD; idx += 256) {
        int i = idx >> 2, h = idx & 3;
        asT_s[h*520 + i] = asp[idx];
    }
    if (t < HIDN) w2_s[t] = w2[t];

    // adjacency column bits (adj | eye): coalesced loads, 4-deep MLP, then ballots
    {
        const int* ab = adj + (size_t)b * NNODE * NNODE + j0 + lane;
        int base = w * 64;
#pragma unroll 4
        for (int c = 0; c < 16; ++c) {
            int i = base + c*4;
            int a0 = ab[(size_t)(i+0) * NNODE];
            int a1 = ab[(size_t)(i+1) * NNODE];
            int a2 = ab[(size_t)(i+2) * NNODE];
            int a3 = ab[(size_t)(i+3) * NNODE];
            unsigned m0 = __ballot_sync(0xffffffffu, (a0 != 0) || (i+0 == j0 + lane));
            unsigned m1 = __ballot_sync(0xffffffffu, (a1 != 0) || (i+1 == j0 + lane));
            unsigned m2 = __ballot_sync(0xffffffffu, (a2 != 0) || (i+2 == j0 + lane));
            unsigned m3 = __ballot_sync(0xffffffffu, (a3 != 0) || (i+3 == j0 + lane));
            if (lane == 0) { mask_s[i] = m0; mask_s[i+1] = m1; mask_s[i+2] = m2; mask_s[i+3] = m3; }
        }
    }
    __syncthreads();

    int h = lane & 3, jslot = lane >> 2;
    int jhalf = w & 1, iq = w >> 1;
    int jl0 = jhalf*16 + jslot*2, jl1 = jl0 + 1;

    float ad0 = ad_buf[((size_t)(b*NNODE) + j0 + jl0)*NHEAD + h];
    float ad1 = ad_buf[((size_t)(b*NNODE) + j0 + jl1)*NHEAD + h];
    float den0 = 0.f, den1 = 0.f;
    ull num0[4] = {0,0,0,0}, num1[4] = {0,0,0,0};
    const ulonglong2* gq2 = (const ulonglong2*)g2_s;   // row = 8 ull2

    const float C06 = 0.8656170246f;   // 0.6 * log2(e)
    const float C04 = 0.5770780164f;   // 0.4 * log2(e)

    int ibeg = iq * 128, iend = ibeg + 128;
#pragma unroll 2
    for (int i = ibeg; i < iend; ++i) {
        float asv   = asT_s[h*520 + i];
        unsigned mw = mask_s[i];
        ulonglong2 ga = gq2[i*8 + h*2];       // LDS.128
        ulonglong2 gb = gq2[i*8 + h*2 + 1];   // LDS.128
        {
            float s = asv + ad0;
            float arg = fmaf(C04, fabsf(s), C06*s);  // log2e*leakyrelu(s,0.2)
            float e = ex2f(arg);
            e = ((mw >> jl0) & 1u) ? e : 0.f;
            den0 += e;
            ull e2 = pack2(e, e);
            num0[0] = fma2(e2, ga.x, num0[0]);
            num0[1] = fma2(e2, ga.y, num0[1]);
            num0[2] = fma2(e2, gb.x, num0[2]);
            num0[3] = fma2(e2, gb.y, num0[3]);
        }
        {
            float s = asv + ad1;
            float arg = fmaf(C04, fabsf(s), C06*s);
            float e = ex2f(arg);
            e = ((mw >> jl1) & 1u) ? e : 0.f;
            den1 += e;
            ull e2 = pack2(e, e);
            num1[0] = fma2(e2, ga.x, num1[0]);
            num1[1] = fma2(e2, ga.y, num1[1]);
            num1[2] = fma2(e2, gb.x, num1[2]);
            num1[3] = fma2(e2, gb.y, num1[3]);
        }
    }
    // per-iq partials
    {
        float* pp = part_s + ((iq*32 + jl0)*4 + h)*9;
        pp[0] = den0;
#pragma unroll
        for (int c = 0; c < 4; ++c) { float2 f = unpack2(num0[c]); pp[1+2*c] = f.x; pp[2+2*c] = f.y; }
        pp = part_s + ((iq*32 + jl1)*4 + h)*9;
        pp[0] = den1;
#pragma unroll
        for (int c = 0; c < 4; ++c) { float2 f = unpack2(num1[c]); pp[1+2*c] = f.x; pp[2+2*c] = f.y; }
    }
    __syncthreads();

    // reduce 4 i-quarters -> h_gnn[j][32] (+bias_g)
    if (t < 128) {
        int jl = t >> 2, hh = t & 3;
        float den = 0.f, nm[8] = {0,0,0,0,0,0,0,0};
#pragma unroll
        for (int q = 0; q < 4; ++q) {
            const float* pp = part_s + ((q*32 + jl)*4 + hh)*9;
            den += pp[0];
#pragma unroll
            for (int c = 0; c < 8; ++c) nm[c] += pp[1+c];
        }
        float inv = __fdividef(1.f, den);   // diag always unmasked => den > 0
#pragma unroll
        for (int c = 0; c < 8; ++c)
            hg_s[jl*33 + hh*8 + c] = fmaf(nm[c], inv, bias_g[hh*8 + c]);
    }
    __syncthreads();

    // ti' = h_gnn@W1[:,:32]^T + b1 (row-major); tj = h_gnn@W1[:,32:]^T (transposed);
    // plus pi/pj = 0.5*sum_h w2[h]*{ti',tj} via warp reduction.
    for (int k = t; k < 32*64; k += 256) {
        int j = k >> 6, o = k & 63;
        const float* wrow = (o < 32) ? (W1 + o*64) : (W1 + (o-32)*64 + 32);
        float acc = (o < 32) ? b1[o] : 0.f;
#pragma unroll
        for (int d = 0; d < 32; ++d) acc = fmaf(hg_s[j*33 + d], wrow[d], acc);
        size_t node = (size_t)(b*NNODE) + j0 + j;
        if (o < 32) {
            ti_buf[node*32 + o] = acc;
        } else {
            int oo = o - 32;
            tjT_buf[(((size_t)b*16 + (oo>>1))*NNODE + j0 + j)*2 + (oo & 1)] = acc;
        }
        // warp holds uniform j and uniform half (o<32 or o>=32)
        float v = acc * w2_s[o & 31];
        v += __shfl_xor_sync(0xffffffffu, v, 16);
        v += __shfl_xor_sync(0xffffffffu, v, 8);
        v += __shfl_xor_sync(0xffffffffu, v, 4);
        v += __shfl_xor_sync(0xffffffffu, v, 2);
        v += __shfl_xor_sync(0xffffffffu, v, 1);
        if (lane == 0) {
            if (o < 32) pi_buf[node] = 0.5f * v;
            else        pj_buf[node] = 0.5f * v;
        }
    }
}

// ================= K4: pairwise edge scorer =================
// sum_h w2*relu(ti+tj) = pi + pj + sum_h (w2/2)*|ti+tj| ; |.| = packed AND.
// lane = j (coalesced); ti broadcast from smem.
#define K4_IT 32
__global__ void __launch_bounds__(256) k4_score(
    const int* __restrict__ adj, const float* __restrict__ w2,
    const float* __restrict__ b2, float* __restrict__ out)
{
    __shared__ ull   ti_s[K4_IT*16];
    __shared__ float pi_s[K4_IT];
    __shared__ ull   w2p_s[16];
    int t = threadIdx.x, lane = t & 31, w = t >> 5;
    int b  = blockIdx.z;
    int i0 = blockIdx.y * K4_IT;
    int j  = blockIdx.x * 256 + w*32 + lane;

    const ull* tiu = (const ull*)ti_buf + ((size_t)(b*NNODE) + i0)*16;
    for (int idx = t; idx < K4_IT*16; idx += 256) ti_s[idx] = tiu[idx];
    if (t < K4_IT) pi_s[t] = pi_buf[(size_t)(b*NNODE) + i0 + t];
    if (t < 16)    w2p_s[t] = pack2(0.5f*w2[2*t], 0.5f*w2[2*t+1]);
    __syncthreads();

    ull tj2[16], w2r[16];
    const ull* tjp = (const ull*)tjT_buf;
#pragma unroll
    for (int p = 0; p < 16; ++p) tj2[p] = tjp[((size_t)b*16 + p)*NNODE + j];
#pragma unroll
    for (int p = 0; p < 16; ++p) w2r[p] = w2p_s[p];
    float pj  = pj_buf[(size_t)(b*NNODE) + j];
    float b2v = b2[0] + pj;

    const int* arow = adj + ((size_t)(b*NNODE) + i0)*NNODE + j;
    float*     orow = out + ((size_t)(b*NNODE) + i0)*NNODE + j;
    const ull ABS2 = 0x7FFFFFFF7FFFFFFFull;

    for (int i = 0; i < K4_IT; ++i) {
        const ulonglong2* tp = (const ulonglong2*)&ti_s[i*16];
        ull a0 = 0, a1 = 0, a2 = 0, a3 = 0;
#pragma unroll
        for (int q = 0; q < 8; ++q) {
            ulonglong2 tv = tp[q];                  // LDS.128 broadcast
            ull s0 = add2(tj2[2*q],   tv.x) & ABS2; // packed |ti+tj|
            ull s1 = add2(tj2[2*q+1], tv.y) & ABS2;
            if (q & 1) {
                a2 = fma2(w2r[2*q],   s0, a2);
                a3 = fma2(w2r[2*q+1], s1, a3);
            } else {
                a0 = fma2(w2r[2*q],   s0, a0);
                a1 = fma2(w2r[2*q+1], s1, a1);
            }
        }
        float2 s0 = unpack2(a0), s1 = unpack2(a1), s2 = unpack2(a2), s3 = unpack2(a3);
        float logit = ((s0.x + s0.y) + (s1.x + s1.y)) + ((s2.x + s2.y) + (s3.x + s3.y))
                    + pi_s[i] + b2v;
        float e  = ex2f(-1.4426950409f * logit);    // exp(-logit)
        float sc = __fdividef(1.f, 1.f + e);

        int ii = i0 + i;
        int av = arow[(size_t)i * NNODE];           // coalesced (lane = j)
        orow[(size_t)i * NNODE] = (av != 0 && ii != j) ? sc : 0.f;
    }
}

// ================= launch =================
extern "C" void kernel_launch(void* const* d_in, const int* in_sizes, int n_in,
                              void* d_out, int out_size)
{
    const float* x        = (const float*)d_in[0];
    const int*   adj      = (const int*)  d_in[1];
    const float* Wp       = (const float*)d_in[2];
    const float* bp       = (const float*)d_in[3];
    const float* Wg       = (const float*)d_in[4];
    const float* att_src  = (const float*)d_in[5];
    const float* att_dst  = (const float*)d_in[6];
    const float* bias_g   = (const float*)d_in[7];
    const float* W1       = (const float*)d_in[8];
    const float* b1       = (const float*)d_in[9];
    const float* w2       = (const float*)d_in[10];
    const float* b2       = (const float*)d_in[11];
    float* out = (float*)d_out;

    k1_embed<<<BB*NNODE/64, 256>>>(x, Wp, bp, Wg, att_src, att_dst);

    cudaFuncSetAttribute(k2_attn, cudaFuncAttributeMaxDynamicSharedMemorySize, SM_TOTAL);
    k2_attn<<<dim3(NNODE/32, BB), 256, SM_TOTAL>>>(adj, bias_g, W1, b1, w2);

    k4_score<<<dim3(2, NNODE/K4_IT, BB), 256>>>(adj, w2, b2, out);
}

// round 4
// speedup vs baseline: 1.0853x; 1.0132x over previous
#include <cuda_runtime.h>

#define BB 16
#define NNODE 512
#define DD 12
#define HIDN 32
#define NHEAD 4
#define CDIM 8

typedef unsigned long long ull;

// ---------------- scratch (no allocs allowed) ----------------
__device__ __align__(16) float g_buf  [BB*NNODE*HIDN];
__device__ __align__(16) float as_buf [BB*NNODE*NHEAD];
__device__ __align__(16) float ad_buf [BB*NNODE*NHEAD];
__device__ __align__(16) float ti_buf [BB*NNODE*HIDN];   // ti + b1 folded, row-major [node][32]
__device__ __align__(16) float tjT_buf[BB*HIDN*NNODE];   // transposed: [(b*16+p)*512 + j] ull pairs
__device__ __align__(16) float pi_buf [BB*NNODE];        // 0.5 * sum_h w2[h]*ti'[node][h]
__device__ __align__(16) float pj_buf [BB*NNODE];        // 0.5 * sum_h w2[h]*tj [node][h]

// ---------------- f32x2 helpers (Blackwell packed fp32) ----------------
__device__ __forceinline__ ull add2(ull a, ull b){ ull r; asm("add.rn.f32x2 %0, %1, %2;" : "=l"(r) : "l"(a), "l"(b)); return r; }
__device__ __forceinline__ ull fma2(ull a, ull b, ull c){ ull r; asm("fma.rn.f32x2 %0, %1, %2, %3;" : "=l"(r) : "l"(a), "l"(b), "l"(c)); return r; }
__device__ __forceinline__ ull pack2(float x, float y){
    ull r; asm("mov.b64 %0, {%1, %2};" : "=l"(r) : "r"(__float_as_uint(x)), "r"(__float_as_uint(y))); return r;
}
__device__ __forceinline__ float2 unpack2(ull v){
    unsigned lo, hi; asm("mov.b64 {%0, %1}, %2;" : "=r"(lo), "=r"(hi) : "l"(v));
    return make_float2(__uint_as_float(lo), __uint_as_float(hi));
}
__device__ __forceinline__ float ex2f(float x){ float r; asm("ex2.approx.f32 %0, %1;" : "=f"(r) : "f"(x)); return r; }

// ================= pad kernels (ncu capture phase-shift) =================
__global__ void pad_k() {}

// ================= K1: per-node embeddings h -> g, a_s, a_d =================
__global__ void __launch_bounds__(256) k1_embed(
    const float* __restrict__ x, const float* __restrict__ Wp, const float* __restrict__ bp,
    const float* __restrict__ Wg, const float* __restrict__ att_src, const float* __restrict__ att_dst)
{
    __shared__ float xs[64*12];
    __shared__ float Wp_s[HIDN*DD];
    __shared__ float bp_s[HIDN];
    __shared__ float Wg_s[HIDN*HIDN];
    __shared__ float asr_s[HIDN], adr_s[HIDN];

    int t  = threadIdx.x;
    int nb = blockIdx.x * 64;

    for (int i = t; i < 64*12; i += 256) xs[i] = x[(size_t)nb*12 + i];
    for (int i = t; i < HIDN*DD; i += 256) Wp_s[i] = Wp[i];
    for (int i = t; i < HIDN*HIDN; i += 256) Wg_s[i] = Wg[i];
    if (t < HIDN) { bp_s[t] = bp[t]; asr_s[t] = att_src[t]; adr_s[t] = att_dst[t]; }
    __syncthreads();

    int n = t & 63, kg = t >> 6;   // kg = k-octet = head index

    float xv[DD];
#pragma unroll
    for (int d = 0; d < DD; ++d) xv[d] = xs[n*DD + d];

    float hv[HIDN];
#pragma unroll
    for (int k = 0; k < HIDN; ++k) {
        float acc = bp_s[k];
#pragma unroll
        for (int d = 0; d < DD; ++d) acc = fmaf(xv[d], Wp_s[k*DD + d], acc);
        hv[k] = fmaxf(acc, 0.f);
    }

    float gv[8];
    float asum = 0.f, adsum = 0.f;
#pragma unroll
    for (int c = 0; c < 8; ++c) {
        int k = kg*8 + c;
        float acc = 0.f;
#pragma unroll
        for (int d = 0; d < HIDN; ++d) acc = fmaf(hv[d], Wg_s[k*HIDN + d], acc);
        gv[c] = acc;
        asum  = fmaf(acc, asr_s[k], asum);
        adsum = fmaf(acc, adr_s[k], adsum);
    }
    int node = nb + n;
    float4* gp = (float4*)(g_buf + (size_t)node*HIDN + kg*8);
    gp[0] = make_float4(gv[0], gv[1], gv[2], gv[3]);
    gp[1] = make_float4(gv[4], gv[5], gv[6], gv[7]);
    as_buf[node*NHEAD + kg] = asum;
    ad_buf[node*NHEAD + kg] = adsum;
}

// ================= K2: attention softmax + h_gnn + ti/tjT + pi/pj =================
// 512 threads, static smem 33KB, g streamed via LDG (L2-hot, 1 line/warp-i).
// Warp w: jq = w&3 (8 j), io = w>>2 (128 i). Lane: h = lane&3, jslot = lane>>2 (1 j).
__global__ void __launch_bounds__(512, 2) k2_attn(
    const int* __restrict__ adj, const float* __restrict__ bias_g,
    const float* __restrict__ W1, const float* __restrict__ b1,
    const float* __restrict__ w2)
{
    __shared__ float    asT_s[4*520];          // a_s transposed, stride 520
    __shared__ unsigned mask_s[NNODE];         // (adj|eye) column bits for 32 j
    __shared__ float    part_s[4*32*4*9];      // 4 i-octants x 32 j x 4 h x (den + 8 num)
    __shared__ float    hg_s[32*33];
    __shared__ float    w2_s[HIDN];

    int t  = threadIdx.x;
    int b  = blockIdx.y;
    int j0 = blockIdx.x * 32;
    int w = t >> 5, lane = t & 31;

    // a_s transposed
    const float* asp = as_buf + (size_t)b * NNODE * NHEAD;
    for (int idx = t; idx < NNODE*NHEAD; idx += 512) {
        int i = idx >> 2, h = idx & 3;
        asT_s[h*520 + i] = asp[idx];
    }
    if (t < HIDN) w2_s[t] = w2[t];

    // adjacency column bits: warp w builds rows [w*32, w*32+32), 4-deep MLP
    {
        const int* ab = adj + (size_t)b * NNODE * NNODE + j0 + lane;
        int base = w * 32;
#pragma unroll
        for (int c = 0; c < 8; ++c) {
            int i = base + c*4;
            int a0 = ab[(size_t)(i+0) * NNODE];
            int a1 = ab[(size_t)(i+1) * NNODE];
            int a2 = ab[(size_t)(i+2) * NNODE];
            int a3 = ab[(size_t)(i+3) * NNODE];
            unsigned m0 = __ballot_sync(0xffffffffu, (a0 != 0) || (i+0 == j0 + lane));
            unsigned m1 = __ballot_sync(0xffffffffu, (a1 != 0) || (i+1 == j0 + lane));
            unsigned m2 = __ballot_sync(0xffffffffu, (a2 != 0) || (i+2 == j0 + lane));
            unsigned m3 = __ballot_sync(0xffffffffu, (a3 != 0) || (i+3 == j0 + lane));
            if (lane == 0) { mask_s[i] = m0; mask_s[i+1] = m1; mask_s[i+2] = m2; mask_s[i+3] = m3; }
        }
    }
    __syncthreads();

    int h = lane & 3, jslot = lane >> 2;
    int jq = w & 3, io = w >> 2;
    int jloc = jq*8 + jslot;

    float adv = ad_buf[((size_t)(b*NNODE) + j0 + jloc)*NHEAD + h];
    float den = 0.f;
    ull num[4] = {0,0,0,0};
    const ulonglong2* gq2 = (const ulonglong2*)(g_buf + (size_t)b * NNODE * HIDN);

    const float C06 = 0.8656170246f;   // 0.6 * log2(e)
    const float C04 = 0.5770780164f;   // 0.4 * log2(e)

    int ibeg = io * 128, iend = ibeg + 128;
#pragma unroll 4
    for (int i = ibeg; i < iend; ++i) {
        float asv   = asT_s[h*520 + i];
        unsigned mw = mask_s[i];
        ulonglong2 ga = gq2[i*8 + h*2];       // LDG.128, 1 L2 line per warp-i
        ulonglong2 gb = gq2[i*8 + h*2 + 1];
        float s = asv + adv;
        float arg = fmaf(C04, fabsf(s), C06*s);  // log2e * leakyrelu(s, 0.2)
        float e = ex2f(arg);
        e = ((mw >> jloc) & 1u) ? e : 0.f;
        den += e;
        ull e2 = pack2(e, e);
        num[0] = fma2(e2, ga.x, num[0]);
        num[1] = fma2(e2, ga.y, num[1]);
        num[2] = fma2(e2, gb.x, num[2]);
        num[3] = fma2(e2, gb.y, num[3]);
    }
    {
        float* pp = part_s + ((io*32 + jloc)*4 + h)*9;
        pp[0] = den;
#pragma unroll
        for (int c = 0; c < 4; ++c) { float2 f = unpack2(num[c]); pp[1+2*c] = f.x; pp[2+2*c] = f.y; }
    }
    __syncthreads();

    // reduce 4 i-octants -> h_gnn[j][32] (+bias_g)
    if (t < 128) {
        int jl = t >> 2, hh = t & 3;
        float dn = 0.f, nm[8] = {0,0,0,0,0,0,0,0};
#pragma unroll
        for (int q = 0; q < 4; ++q) {
            const float* pp = part_s + ((q*32 + jl)*4 + hh)*9;
            dn += pp[0];
#pragma unroll
            for (int c = 0; c < 8; ++c) nm[c] += pp[1+c];
        }
        float inv = __fdividef(1.f, dn);    // diag always unmasked => dn > 0
#pragma unroll
        for (int c = 0; c < 8; ++c)
            hg_s[jl*33 + hh*8 + c] = fmaf(nm[c], inv, bias_g[hh*8 + c]);
    }
    __syncthreads();

    // ti' = h_gnn@W1[:,:32]^T + b1 (row-major); tj = h_gnn@W1[:,32:]^T (transposed);
    // pi/pj = 0.5*sum_h w2[h]*{ti',tj} via warp reduction (warp-uniform j & half).
    for (int k = t; k < 32*64; k += 512) {
        int j = k >> 6, o = k & 63;
        const float* wrow = (o < 32) ? (W1 + o*64) : (W1 + (o-32)*64 + 32);
        float acc = (o < 32) ? b1[o] : 0.f;
#pragma unroll
        for (int d = 0; d < 32; ++d) acc = fmaf(hg_s[j*33 + d], wrow[d], acc);
        size_t node = (size_t)(b*NNODE) + j0 + j;
        if (o < 32) {
            ti_buf[node*32 + o] = acc;
        } else {
            int oo = o - 32;
            tjT_buf[(((size_t)b*16 + (oo>>1))*NNODE + j0 + j)*2 + (oo & 1)] = acc;
        }
        float v = acc * w2_s[o & 31];
        v += __shfl_xor_sync(0xffffffffu, v, 16);
        v += __shfl_xor_sync(0xffffffffu, v, 8);
        v += __shfl_xor_sync(0xffffffffu, v, 4);
        v += __shfl_xor_sync(0xffffffffu, v, 2);
        v += __shfl_xor_sync(0xffffffffu, v, 1);
        if (lane == 0) {
            if (o < 32) pi_buf[node] = 0.5f * v;
            else        pj_buf[node] = 0.5f * v;
        }
    }
}

// ================= K4: pairwise edge scorer =================
// sum_h w2*relu(ti+tj) = pi + pj + sum_h (w2/2)*|ti+tj| ; |.| = packed AND.
#define K4_IT 32
__global__ void __launch_bounds__(256) k4_score(
    const int* __restrict__ adj, const float* __restrict__ w2,
    const float* __restrict__ b2, float* __restrict__ out)
{
    __shared__ ull   ti_s[K4_IT*16];
    __shared__ float pi_s[K4_IT];
    __shared__ ull   w2p_s[16];
    int t = threadIdx.x, lane = t & 31, w = t >> 5;
    int b  = blockIdx.z;
    int i0 = blockIdx.y * K4_IT;
    int j  = blockIdx.x * 256 + w*32 + lane;

    const ull* tiu = (const ull*)ti_buf + ((size_t)(b*NNODE) + i0)*16;
    for (int idx = t; idx < K4_IT*16; idx += 256) ti_s[idx] = tiu[idx];
    if (t < K4_IT) pi_s[t] = pi_buf[(size_t)(b*NNODE) + i0 + t];
    if (t < 16)    w2p_s[t] = pack2(0.5f*w2[2*t], 0.5f*w2[2*t+1]);
    __syncthreads();

    ull tj2[16], w2r[16];
    const ull* tjp = (const ull*)tjT_buf;
#pragma unroll
    for (int p = 0; p < 16; ++p) tj2[p] = tjp[((size_t)b*16 + p)*NNODE + j];
#pragma unroll
    for (int p = 0; p < 16; ++p) w2r[p] = w2p_s[p];
    float pj  = pj_buf[(size_t)(b*NNODE) + j];
    float b2v = b2[0] + pj;

    const int* arow = adj + ((size_t)(b*NNODE) + i0)*NNODE + j;
    float*     orow = out + ((size_t)(b*NNODE) + i0)*NNODE + j;
    const ull ABS2 = 0x7FFFFFFF7FFFFFFFull;

    for (int i = 0; i < K4_IT; ++i) {
        const ulonglong2* tp = (const ulonglong2*)&ti_s[i*16];
        ull a0 = 0, a1 = 0, a2 = 0, a3 = 0;
#pragma unroll
        for (int q = 0; q < 8; ++q) {
            ulonglong2 tv = tp[q];                  // LDS.128 broadcast
            ull s0 = add2(tj2[2*q],   tv.x) & ABS2; // packed |ti+tj|
            ull s1 = add2(tj2[2*q+1], tv.y) & ABS2;
            if (q & 1) {
                a2 = fma2(w2r[2*q],   s0, a2);
                a3 = fma2(w2r[2*q+1], s1, a3);
            } else {
                a0 = fma2(w2r[2*q],   s0, a0);
                a1 = fma2(w2r[2*q+1], s1, a1);
            }
        }
        float2 s0 = unpack2(a0), s1 = unpack2(a1), s2 = unpack2(a2), s3 = unpack2(a3);
        float logit = ((s0.x + s0.y) + (s1.x + s1.y)) + ((s2.x + s2.y) + (s3.x + s3.y))
                    + pi_s[i] + b2v;
        float e  = ex2f(-1.4426950409f * logit);    // exp(-logit)
        float sc = __fdividef(1.f, 1.f + e);

        int ii = i0 + i;
        int av = arow[(size_t)i * NNODE];           // coalesced (lane = j)
        orow[(size_t)i * NNODE] = (av != 0 && ii != j) ? sc : 0.f;
    }
}

// ================= launch =================
extern "C" void kernel_launch(void* const* d_in, const int* in_sizes, int n_in,
                              void* d_out, int out_size)
{
    const float* x        = (const float*)d_in[0];
    const int*   adj      = (const int*)  d_in[1];
    const float* Wp       = (const float*)d_in[2];
    const float* bp       = (const float*)d_in[3];
    const float* Wg       = (const float*)d_in[4];
    const float* att_src  = (const float*)d_in[5];
    const float* att_dst  = (const float*)d_in[6];
    const float* bias_g   = (const float*)d_in[7];
    const float* W1       = (const float*)d_in[8];
    const float* b1       = (const float*)d_in[9];
    const float* w2       = (const float*)d_in[10];
    const float* b2       = (const float*)d_in[11];
    float* out = (float*)d_out;

    // two pads shift the ncu -s 5 capture slot onto k2 (diagnostic)
    pad_k<<<1, 32>>>();
    pad_k<<<1, 32>>>();

    k1_embed<<<BB*NNODE/64, 256>>>(x, Wp, bp, Wg, att_src, att_dst);

    k2_attn<<<dim3(NNODE/32, BB), 512>>>(adj, bias_g, W1, b1, w2);

    k4_score<<<dim3(2, NNODE/K4_IT, BB), 256>>>(adj, w2, b2, out);
}

// round 5
// speedup vs baseline: 2.1386x; 1.9705x over previous
#include <cuda_runtime.h>

#define BB 16
#define NNODE 512
#define DD 12
#define HIDN 32
#define NHEAD 4
#define CDIM 8

typedef unsigned long long ull;

// ---------------- scratch (no allocs allowed) ----------------
__device__ __align__(16) float g_buf  [BB*NNODE*HIDN];
__device__ __align__(16) float as_buf [BB*NNODE*NHEAD];
__device__ __align__(16) float ad_buf [BB*NNODE*NHEAD];
__device__ __align__(16) float ti_buf [BB*NNODE*HIDN];   // ti + b1 folded, row-major [node][32]
__device__ __align__(16) float tjT_buf[BB*HIDN*NNODE];   // transposed: [(b*16+p)*512 + j] ull pairs
__device__ __align__(16) float pi_buf [BB*NNODE];        // 0.5 * sum_h w2[h]*ti'[node][h]
__device__ __align__(16) float pj_buf [BB*NNODE];        // 0.5 * sum_h w2[h]*tj [node][h]

// ---------------- f32x2 helpers (Blackwell packed fp32) ----------------
__device__ __forceinline__ ull add2(ull a, ull b){ ull r; asm("add.rn.f32x2 %0, %1, %2;" : "=l"(r) : "l"(a), "l"(b)); return r; }
__device__ __forceinline__ ull fma2(ull a, ull b, ull c){ ull r; asm("fma.rn.f32x2 %0, %1, %2, %3;" : "=l"(r) : "l"(a), "l"(b), "l"(c)); return r; }
__device__ __forceinline__ ull pack2(float x, float y){
    ull r; asm("mov.b64 %0, {%1, %2};" : "=l"(r) : "r"(__float_as_uint(x)), "r"(__float_as_uint(y))); return r;
}
__device__ __forceinline__ float2 unpack2(ull v){
    unsigned lo, hi; asm("mov.b64 {%0, %1}, %2;" : "=r"(lo), "=r"(hi) : "l"(v));
    return make_float2(__uint_as_float(lo), __uint_as_float(hi));
}
__device__ __forceinline__ float ex2f(float x){ float r; asm("ex2.approx.f32 %0, %1;" : "=f"(r) : "f"(x)); return r; }

// ================= pad kernels (ncu capture phase-shift) =================
__global__ void pad_k() {}

// ================= K1: per-node embeddings h -> g, a_s, a_d =================
// 256 blocks x 128 threads; 32 nodes/block; thread = (node, head).
__global__ void __launch_bounds__(128) k1_embed(
    const float* __restrict__ x, const float* __restrict__ Wp, const float* __restrict__ bp,
    const float* __restrict__ Wg, const float* __restrict__ att_src, const float* __restrict__ att_dst)
{
    __shared__ float xs[32*12];
    __shared__ float Wp_s[HIDN*DD];
    __shared__ float bp_s[HIDN];
    __shared__ float Wg_s[HIDN*HIDN];
    __shared__ float asr_s[HIDN], adr_s[HIDN];

    int t  = threadIdx.x;
    int nb = blockIdx.x * 32;

    for (int i = t; i < 32*12; i += 128) xs[i] = x[(size_t)nb*12 + i];
    for (int i = t; i < HIDN*DD; i += 128) Wp_s[i] = Wp[i];
    for (int i = t; i < HIDN*HIDN; i += 128) Wg_s[i] = Wg[i];
    if (t < HIDN) { bp_s[t] = bp[t]; asr_s[t] = att_src[t]; adr_s[t] = att_dst[t]; }
    __syncthreads();

    int n = t & 31, kg = t >> 5;   // kg = head index

    float xv[DD];
#pragma unroll
    for (int d = 0; d < DD; ++d) xv[d] = xs[n*DD + d];

    float hv[HIDN];
#pragma unroll
    for (int k = 0; k < HIDN; ++k) {
        float acc = bp_s[k];
#pragma unroll
        for (int d = 0; d < DD; ++d) acc = fmaf(xv[d], Wp_s[k*DD + d], acc);
        hv[k] = fmaxf(acc, 0.f);
    }

    float gv[8];
    float asum = 0.f, adsum = 0.f;
#pragma unroll
    for (int c = 0; c < 8; ++c) {
        int k = kg*8 + c;
        float acc = 0.f;
#pragma unroll
        for (int d = 0; d < HIDN; ++d) acc = fmaf(hv[d], Wg_s[k*HIDN + d], acc);
        gv[c] = acc;
        asum  = fmaf(acc, asr_s[k], asum);
        adsum = fmaf(acc, adr_s[k], adsum);
    }
    int node = nb + n;
    float4* gp = (float4*)(g_buf + (size_t)node*HIDN + kg*8);
    gp[0] = make_float4(gv[0], gv[1], gv[2], gv[3]);
    gp[1] = make_float4(gv[4], gv[5], gv[6], gv[7]);
    as_buf[node*NHEAD + kg] = asum;
    ad_buf[node*NHEAD + kg] = adsum;
}

// ================= K2: attention softmax + h_gnn + ti/tjT + pi/pj =================
// 512 threads. g streamed via LDG; W1 staged transposed in smem (conflict-free).
__global__ void __launch_bounds__(512, 2) k2_attn(
    const int* __restrict__ adj, const float* __restrict__ bias_g,
    const float* __restrict__ W1, const float* __restrict__ b1,
    const float* __restrict__ w2)
{
    __shared__ float    asT_s[4*520];          // a_s transposed, stride 520
    __shared__ unsigned mask_s[NNODE];         // (adj|eye) column bits for 32 j
    __shared__ float    part_s[4*32*4*9];      // 4 i-octants x 32 j x 4 h x (den + 8 num)
    __shared__ float    hg_s[32*33];
    __shared__ float    w2_s[HIDN];
    __shared__ float    W1T_s[32*65];          // W1T[d][o], pad 65: conflict-free LDS

    int t  = threadIdx.x;
    int b  = blockIdx.y;
    int j0 = blockIdx.x * 32;
    int w = t >> 5, lane = t & 31;

    // a_s transposed
    const float* asp = as_buf + (size_t)b * NNODE * NHEAD;
    for (int idx = t; idx < NNODE*NHEAD; idx += 512) {
        int i = idx >> 2, h = idx & 3;
        asT_s[h*520 + i] = asp[idx];
    }
    if (t < HIDN) w2_s[t] = w2[t];

    // W1 -> smem transposed: VT[d][o]; o<32: W1[o*64+d]; o>=32: W1[(o-32)*64+32+d]
    for (int idx = t; idx < 32*64; idx += 512) {
        int r = idx >> 6, c = idx & 63;     // W1[r][c], coalesced read
        int d = (c < 32) ? c : (c - 32);
        int o = (c < 32) ? r : (r + 32);
        W1T_s[d*65 + o] = W1[idx];
    }

    // adjacency column bits: warp w builds rows [w*32, w*32+32), 4-deep MLP
    {
        const int* ab = adj + (size_t)b * NNODE * NNODE + j0 + lane;
        int base = w * 32;
#pragma unroll
        for (int c = 0; c < 8; ++c) {
            int i = base + c*4;
            int a0 = ab[(size_t)(i+0) * NNODE];
            int a1 = ab[(size_t)(i+1) * NNODE];
            int a2 = ab[(size_t)(i+2) * NNODE];
            int a3 = ab[(size_t)(i+3) * NNODE];
            unsigned m0 = __ballot_sync(0xffffffffu, (a0 != 0) || (i+0 == j0 + lane));
            unsigned m1 = __ballot_sync(0xffffffffu, (a1 != 0) || (i+1 == j0 + lane));
            unsigned m2 = __ballot_sync(0xffffffffu, (a2 != 0) || (i+2 == j0 + lane));
            unsigned m3 = __ballot_sync(0xffffffffu, (a3 != 0) || (i+3 == j0 + lane));
            if (lane == 0) { mask_s[i] = m0; mask_s[i+1] = m1; mask_s[i+2] = m2; mask_s[i+3] = m3; }
        }
    }
    __syncthreads();

    int h = lane & 3, jslot = lane >> 2;
    int jq = w & 3, io = w >> 2;
    int jloc = jq*8 + jslot;

    float adv = ad_buf[((size_t)(b*NNODE) + j0 + jloc)*NHEAD + h];
    float den = 0.f;
    ull num[4] = {0,0,0,0};
    const ulonglong2* gq2 = (const ulonglong2*)(g_buf + (size_t)b * NNODE * HIDN);

    const float C06 = 0.8656170246f;   // 0.6 * log2(e)
    const float C04 = 0.5770780164f;   // 0.4 * log2(e)

    int ibeg = io * 128, iend = ibeg + 128;
#pragma unroll 4
    for (int i = ibeg; i < iend; ++i) {
        float asv   = asT_s[h*520 + i];
        unsigned mw = mask_s[i];
        ulonglong2 ga = gq2[i*8 + h*2];       // LDG.128, one L2 line per warp-i
        ulonglong2 gb = gq2[i*8 + h*2 + 1];
        float s = asv + adv;
        float arg = fmaf(C04, fabsf(s), C06*s);  // log2e * leakyrelu(s, 0.2)
        float e = ex2f(arg);
        e = ((mw >> jloc) & 1u) ? e : 0.f;
        den += e;
        ull e2 = pack2(e, e);
        num[0] = fma2(e2, ga.x, num[0]);
        num[1] = fma2(e2, ga.y, num[1]);
        num[2] = fma2(e2, gb.x, num[2]);
        num[3] = fma2(e2, gb.y, num[3]);
    }
    {
        float* pp = part_s + ((io*32 + jloc)*4 + h)*9;
        pp[0] = den;
#pragma unroll
        for (int c = 0; c < 4; ++c) { float2 f = unpack2(num[c]); pp[1+2*c] = f.x; pp[2+2*c] = f.y; }
    }
    __syncthreads();

    // reduce 4 i-octants -> h_gnn[j][32] (+bias_g)
    if (t < 128) {
        int jl = t >> 2, hh = t & 3;
        float dn = 0.f, nm[8] = {0,0,0,0,0,0,0,0};
#pragma unroll
        for (int q = 0; q < 4; ++q) {
            const float* pp = part_s + ((q*32 + jl)*4 + hh)*9;
            dn += pp[0];
#pragma unroll
            for (int c = 0; c < 8; ++c) nm[c] += pp[1+c];
        }
        float inv = __fdividef(1.f, dn);    // diag always unmasked => dn > 0
#pragma unroll
        for (int c = 0; c < 8; ++c)
            hg_s[jl*33 + hh*8 + c] = fmaf(nm[c], inv, bias_g[hh*8 + c]);
    }
    __syncthreads();

    // ti' = h_gnn@W1[:,:32]^T + b1 (row-major); tj = h_gnn@W1[:,32:]^T (transposed);
    // W1 from smem transposed: lanes sweep o -> conflict-free; hg broadcast.
    for (int k = t; k < 32*64; k += 512) {
        int j = k >> 6, o = k & 63;
        float acc = (o < 32) ? b1[o] : 0.f;
#pragma unroll
        for (int d = 0; d < 32; ++d) acc = fmaf(hg_s[j*33 + d], W1T_s[d*65 + o], acc);
        size_t node = (size_t)(b*NNODE) + j0 + j;
        if (o < 32) {
            ti_buf[node*32 + o] = acc;
        } else {
            int oo = o - 32;
            tjT_buf[(((size_t)b*16 + (oo>>1))*NNODE + j0 + j)*2 + (oo & 1)] = acc;
        }
        float v = acc * w2_s[o & 31];
        v += __shfl_xor_sync(0xffffffffu, v, 16);
        v += __shfl_xor_sync(0xffffffffu, v, 8);
        v += __shfl_xor_sync(0xffffffffu, v, 4);
        v += __shfl_xor_sync(0xffffffffu, v, 2);
        v += __shfl_xor_sync(0xffffffffu, v, 1);
        if (lane == 0) {
            if (o < 32) pi_buf[node] = 0.5f * v;
            else        pj_buf[node] = 0.5f * v;
        }
    }
}

// ================= K4: pairwise edge scorer =================
// sum_h w2*relu(ti+tj) = pi + pj + sum_h (w2/2)*|ti+tj| ; |.| = packed AND.
#define K4_IT 32
__global__ void __launch_bounds__(256) k4_score(
    const int* __restrict__ adj, const float* __restrict__ w2,
    const float* __restrict__ b2, float* __restrict__ out)
{
    __shared__ ull   ti_s[K4_IT*16];
    __shared__ float pi_s[K4_IT];
    __shared__ ull   w2p_s[16];
    int t = threadIdx.x, lane = t & 31, w = t >> 5;
    int b  = blockIdx.z;
    int i0 = blockIdx.y * K4_IT;
    int j  = blockIdx.x * 256 + w*32 + lane;

    const ull* tiu = (const ull*)ti_buf + ((size_t)(b*NNODE) + i0)*16;
    for (int idx = t; idx < K4_IT*16; idx += 256) ti_s[idx] = tiu[idx];
    if (t < K4_IT) pi_s[t] = pi_buf[(size_t)(b*NNODE) + i0 + t];
    if (t < 16)    w2p_s[t] = pack2(0.5f*w2[2*t], 0.5f*w2[2*t+1]);
    __syncthreads();

    ull tj2[16], w2r[16];
    const ull* tjp = (const ull*)tjT_buf;
#pragma unroll
    for (int p = 0; p < 16; ++p) tj2[p] = tjp[((size_t)b*16 + p)*NNODE + j];
#pragma unroll
    for (int p = 0; p < 16; ++p) w2r[p] = w2p_s[p];
    float pj  = pj_buf[(size_t)(b*NNODE) + j];
    float b2v = b2[0] + pj;

    const int* arow = adj + ((size_t)(b*NNODE) + i0)*NNODE + j;
    float*     orow = out + ((size_t)(b*NNODE) + i0)*NNODE + j;
    const ull ABS2 = 0x7FFFFFFF7FFFFFFFull;

    for (int i = 0; i < K4_IT; ++i) {
        const ulonglong2* tp = (const ulonglong2*)&ti_s[i*16];
        ull a0 = 0, a1 = 0, a2 = 0, a3 = 0;
#pragma unroll
        for (int q = 0; q < 8; ++q) {
            ulonglong2 tv = tp[q];                  // LDS.128 broadcast
            ull s0 = add2(tj2[2*q],   tv.x) & ABS2; // packed |ti+tj|
            ull s1 = add2(tj2[2*q+1], tv.y) & ABS2;
            if (q & 1) {
                a2 = fma2(w2r[2*q],   s0, a2);
                a3 = fma2(w2r[2*q+1], s1, a3);
            } else {
                a0 = fma2(w2r[2*q],   s0, a0);
                a1 = fma2(w2r[2*q+1], s1, a1);
            }
        }
        float2 s0 = unpack2(a0), s1 = unpack2(a1), s2 = unpack2(a2), s3 = unpack2(a3);
        float logit = ((s0.x + s0.y) + (s1.x + s1.y)) + ((s2.x + s2.y) + (s3.x + s3.y))
                    + pi_s[i] + b2v;
        float e  = ex2f(-1.4426950409f * logit);    // exp(-logit)
        float sc = __fdividef(1.f, 1.f + e);

        int ii = i0 + i;
        int av = arow[(size_t)i * NNODE];           // coalesced (lane = j)
        orow[(size_t)i * NNODE] = (av != 0 && ii != j) ? sc : 0.f;
    }
}

// ================= launch =================
extern "C" void kernel_launch(void* const* d_in, const int* in_sizes, int n_in,
                              void* d_out, int out_size)
{
    const float* x        = (const float*)d_in[0];
    const int*   adj      = (const int*)  d_in[1];
    const float* Wp       = (const float*)d_in[2];
    const float* bp       = (const float*)d_in[3];
    const float* Wg       = (const float*)d_in[4];
    const float* att_src  = (const float*)d_in[5];
    const float* att_dst  = (const float*)d_in[6];
    const float* bias_g   = (const float*)d_in[7];
    const float* W1       = (const float*)d_in[8];
    const float* b1       = (const float*)d_in[9];
    const float* w2       = (const float*)d_in[10];
    const float* b2       = (const float*)d_in[11];
    float* out = (float*)d_out;

    // two pads keep the ncu -s 5 capture slot on k2
    pad_k<<<1, 32>>>();
    pad_k<<<1, 32>>>();

    k1_embed<<<BB*NNODE/32, 128>>>(x, Wp, bp, Wg, att_src, att_dst);

    k2_attn<<<dim3(NNODE/32, BB), 512>>>(adj, bias_g, W1, b1, w2);

    k4_score<<<dim3(2, NNODE/K4_IT, BB), 256>>>(adj, w2, b2, out);
}

// round 6
// speedup vs baseline: 2.3606x; 1.1038x over previous
#include <cuda_runtime.h>

#define BB 16
#define NNODE 512
#define DD 12
#define HIDN 32
#define NHEAD 4
#define CDIM 8

typedef unsigned long long ull;

// ---------------- scratch (no allocs allowed) ----------------
__device__ __align__(16) float g_buf  [BB*NNODE*HIDN];
__device__ __align__(16) float as_buf [BB*NNODE*NHEAD];
__device__ __align__(16) float ad_buf [BB*NNODE*NHEAD];
__device__ __align__(16) float ti_buf [BB*NNODE*HIDN];   // ti + b1 folded, row-major [node][32]
__device__ __align__(16) float tjT_buf[BB*HIDN*NNODE];   // transposed: [(b*16+p)*512 + j] ull pairs
__device__ __align__(16) float pi_buf [BB*NNODE];        // 0.5 * sum_h w2[h]*ti'[node][h]
__device__ __align__(16) float pj_buf [BB*NNODE];        // 0.5 * sum_h w2[h]*tj [node][h]

// ---------------- f32x2 helpers (Blackwell packed fp32) ----------------
__device__ __forceinline__ ull add2(ull a, ull b){ ull r; asm("add.rn.f32x2 %0, %1, %2;" : "=l"(r) : "l"(a), "l"(b)); return r; }
__device__ __forceinline__ ull fma2(ull a, ull b, ull c){ ull r; asm("fma.rn.f32x2 %0, %1, %2, %3;" : "=l"(r) : "l"(a), "l"(b), "l"(c)); return r; }
__device__ __forceinline__ ull pack2(float x, float y){
    ull r; asm("mov.b64 %0, {%1, %2};" : "=l"(r) : "r"(__float_as_uint(x)), "r"(__float_as_uint(y))); return r;
}
__device__ __forceinline__ float2 unpack2(ull v){
    unsigned lo, hi; asm("mov.b64 {%0, %1}, %2;" : "=r"(lo), "=r"(hi) : "l"(v));
    return make_float2(__uint_as_float(lo), __uint_as_float(hi));
}
__device__ __forceinline__ float ex2f(float x){ float r; asm("ex2.approx.f32 %0, %1;" : "=f"(r) : "f"(x)); return r; }

// ================= pad kernel (ncu capture phase-shift) =================
__global__ void pad_k() {}

// ================= K1: per-node embeddings h -> g, a_s, a_d =================
// 256 blocks x 128 threads; 32 nodes/block; thread = (node, head).
__global__ void __launch_bounds__(128) k1_embed(
    const float* __restrict__ x, const float* __restrict__ Wp, const float* __restrict__ bp,
    const float* __restrict__ Wg, const float* __restrict__ att_src, const float* __restrict__ att_dst)
{
    __shared__ float xs[32*12];
    __shared__ float Wp_s[HIDN*DD];
    __shared__ float bp_s[HIDN];
    __shared__ float Wg_s[HIDN*HIDN];
    __shared__ float asr_s[HIDN], adr_s[HIDN];

    int t  = threadIdx.x;
    int nb = blockIdx.x * 32;

    for (int i = t; i < 32*12; i += 128) xs[i] = x[(size_t)nb*12 + i];
    for (int i = t; i < HIDN*DD; i += 128) Wp_s[i] = Wp[i];
    for (int i = t; i < HIDN*HIDN; i += 128) Wg_s[i] = Wg[i];
    if (t < HIDN) { bp_s[t] = bp[t]; asr_s[t] = att_src[t]; adr_s[t] = att_dst[t]; }
    __syncthreads();

    int n = t & 31, kg = t >> 5;   // kg = head index

    float xv[DD];
#pragma unroll
    for (int d = 0; d < DD; ++d) xv[d] = xs[n*DD + d];

    float hv[HIDN];
#pragma unroll
    for (int k = 0; k < HIDN; ++k) {
        float acc = bp_s[k];
#pragma unroll
        for (int d = 0; d < DD; ++d) acc = fmaf(xv[d], Wp_s[k*DD + d], acc);
        hv[k] = fmaxf(acc, 0.f);
    }

    float gv[8];
    float asum = 0.f, adsum = 0.f;
#pragma unroll
    for (int c = 0; c < 8; ++c) {
        int k = kg*8 + c;
        float acc = 0.f;
#pragma unroll
        for (int d = 0; d < HIDN; ++d) acc = fmaf(hv[d], Wg_s[k*HIDN + d], acc);
        gv[c] = acc;
        asum  = fmaf(acc, asr_s[k], asum);
        adsum = fmaf(acc, adr_s[k], adsum);
    }
    int node = nb + n;
    float4* gp = (float4*)(g_buf + (size_t)node*HIDN + kg*8);
    gp[0] = make_float4(gv[0], gv[1], gv[2], gv[3]);
    gp[1] = make_float4(gv[4], gv[5], gv[6], gv[7]);
    as_buf[node*NHEAD + kg] = asum;
    ad_buf[node*NHEAD + kg] = adsum;
}

// ================= K2: attention softmax + h_gnn + ti/tjT + pi/pj =================
// 512 threads, dynamic smem ~94.5KB (2 blocks/SM).
// Warp w = private 32-i segment; covers ALL 32 j (4 j-groups per lane, g regs reused).
// Lane: h = lane&3, jslot = lane>>2 (0..7); j-groups jloc = g*8+jslot, g=0..3.
#define SM_PART  0                          // 16*32*4*9*4   = 73728
#define SM_AST   73728                      // 4*520*4       = 8320
#define SM_MASK  82048                      // 512*4         = 2048
#define SM_HG    84096                      // 32*33*4       = 4224
#define SM_W2    88320                      // 128
#define SM_W1T   88448                      // 32*65*4       = 8320
#define SM_TOTAL 96768

__global__ void __launch_bounds__(512, 2) k2_attn(
    const int* __restrict__ adj, const float* __restrict__ bias_g,
    const float* __restrict__ W1, const float* __restrict__ b1,
    const float* __restrict__ w2)
{
    extern __shared__ char sm[];
    float*    part_s = (float*) (sm + SM_PART);
    float*    asT_s  = (float*) (sm + SM_AST);
    unsigned* mask_s = (unsigned*)(sm + SM_MASK);
    float*    hg_s   = (float*) (sm + SM_HG);
    float*    w2_s   = (float*) (sm + SM_W2);
    float*    W1T_s  = (float*) (sm + SM_W1T);

    int t  = threadIdx.x;
    int b  = blockIdx.y;
    int j0 = blockIdx.x * 32;
    int w = t >> 5, lane = t & 31;

    // a_s transposed
    const float* asp = as_buf + (size_t)b * NNODE * NHEAD;
    for (int idx = t; idx < NNODE*NHEAD; idx += 512) {
        int i = idx >> 2, h = idx & 3;
        asT_s[h*520 + i] = asp[idx];
    }
    if (t < HIDN) w2_s[t] = w2[t];

    // W1 -> smem transposed: W1T[d][o]; o<32: W1[o*64+d]; o>=32: W1[(o-32)*64+32+d]
    for (int idx = t; idx < 32*64; idx += 512) {
        int r = idx >> 6, c = idx & 63;     // W1[r][c], coalesced read
        int d = (c < 32) ? c : (c - 32);
        int o = (c < 32) ? r : (r + 32);
        W1T_s[d*65 + o] = W1[idx];
    }

    // adjacency column bits: warp w builds rows [w*32, w*32+32), 4-deep MLP
    {
        const int* ab = adj + (size_t)b * NNODE * NNODE + j0 + lane;
        int base = w * 32;
#pragma unroll
        for (int c = 0; c < 8; ++c) {
            int i = base + c*4;
            int a0 = ab[(size_t)(i+0) * NNODE];
            int a1 = ab[(size_t)(i+1) * NNODE];
            int a2 = ab[(size_t)(i+2) * NNODE];
            int a3 = ab[(size_t)(i+3) * NNODE];
            unsigned m0 = __ballot_sync(0xffffffffu, (a0 != 0) || (i+0 == j0 + lane));
            unsigned m1 = __ballot_sync(0xffffffffu, (a1 != 0) || (i+1 == j0 + lane));
            unsigned m2 = __ballot_sync(0xffffffffu, (a2 != 0) || (i+2 == j0 + lane));
            unsigned m3 = __ballot_sync(0xffffffffu, (a3 != 0) || (i+3 == j0 + lane));
            if (lane == 0) { mask_s[i] = m0; mask_s[i+1] = m1; mask_s[i+2] = m2; mask_s[i+3] = m3; }
        }
    }
    __syncthreads();

    int h = lane & 3, jslot = lane >> 2;

    // ad for this lane's 4 j-groups
    float adv[4];
#pragma unroll
    for (int g = 0; g < 4; ++g)
        adv[g] = ad_buf[((size_t)(b*NNODE) + j0 + g*8 + jslot)*NHEAD + h];
    unsigned bit0 = 1u << jslot;

    float den[4] = {0,0,0,0};
    ull num[16];
#pragma unroll
    for (int q = 0; q < 16; ++q) num[q] = 0ull;

    const ulonglong2* gq2 = (const ulonglong2*)(g_buf + (size_t)b * NNODE * HIDN);

    const float C06 = 0.8656170246f;   // 0.6 * log2(e)
    const float C04 = 0.5770780164f;   // 0.4 * log2(e)

    int ibeg = w * 32, iend = ibeg + 32;
#pragma unroll 2
    for (int i = ibeg; i < iend; ++i) {
        float asv   = asT_s[h*520 + i];
        unsigned mw = mask_s[i];
        ulonglong2 ga = gq2[i*8 + h*2];       // LDG.128, one L2 line per warp-i
        ulonglong2 gb = gq2[i*8 + h*2 + 1];
#pragma unroll
        for (int g = 0; g < 4; ++g) {
            float s = asv + adv[g];
            float arg = fmaf(C04, fabsf(s), C06*s);  // log2e * leakyrelu(s, 0.2)
            float e = ex2f(arg);
            e = (mw & (bit0 << (8*g))) ? e : 0.f;
            den[g] += e;
            ull e2 = pack2(e, e);
            num[4*g+0] = fma2(e2, ga.x, num[4*g+0]);
            num[4*g+1] = fma2(e2, ga.y, num[4*g+1]);
            num[4*g+2] = fma2(e2, gb.x, num[4*g+2]);
            num[4*g+3] = fma2(e2, gb.y, num[4*g+3]);
        }
    }
#pragma unroll
    for (int g = 0; g < 4; ++g) {
        float* pp = part_s + ((w*32 + g*8 + jslot)*4 + h)*9;
        pp[0] = den[g];
#pragma unroll
        for (int c = 0; c < 4; ++c) {
            float2 f = unpack2(num[4*g+c]); pp[1+2*c] = f.x; pp[2+2*c] = f.y;
        }
    }
    __syncthreads();

    // reduce 16 i-segments -> h_gnn[j][32] (+bias_g)
    if (t < 128) {
        int jl = t >> 2, hh = t & 3;
        float dn = 0.f, nm[8] = {0,0,0,0,0,0,0,0};
#pragma unroll
        for (int q = 0; q < 16; ++q) {
            const float* pp = part_s + ((q*32 + jl)*4 + hh)*9;
            dn += pp[0];
#pragma unroll
            for (int c = 0; c < 8; ++c) nm[c] += pp[1+c];
        }
        float inv = __fdividef(1.f, dn);    // diag always unmasked => dn > 0
#pragma unroll
        for (int c = 0; c < 8; ++c)
            hg_s[jl*33 + hh*8 + c] = fmaf(nm[c], inv, bias_g[hh*8 + c]);
    }
    __syncthreads();

    // ti' = h_gnn@W1[:,:32]^T + b1 (row-major); tj = h_gnn@W1[:,32:]^T (transposed);
    // W1 from smem transposed: lanes sweep o -> conflict-free; hg broadcast.
    for (int k = t; k < 32*64; k += 512) {
        int j = k >> 6, o = k & 63;
        float acc = (o < 32) ? b1[o] : 0.f;
#pragma unroll
        for (int d = 0; d < 32; ++d) acc = fmaf(hg_s[j*33 + d], W1T_s[d*65 + o], acc);
        size_t node = (size_t)(b*NNODE) + j0 + j;
        if (o < 32) {
            ti_buf[node*32 + o] = acc;
        } else {
            int oo = o - 32;
            tjT_buf[(((size_t)b*16 + (oo>>1))*NNODE + j0 + j)*2 + (oo & 1)] = acc;
        }
        float v = acc * w2_s[o & 31];
        v += __shfl_xor_sync(0xffffffffu, v, 16);
        v += __shfl_xor_sync(0xffffffffu, v, 8);
        v += __shfl_xor_sync(0xffffffffu, v, 4);
        v += __shfl_xor_sync(0xffffffffu, v, 2);
        v += __shfl_xor_sync(0xffffffffu, v, 1);
        if (lane == 0) {
            if (o < 32) pi_buf[node] = 0.5f * v;
            else        pj_buf[node] = 0.5f * v;
        }
    }
}

// ================= K4: pairwise edge scorer =================
// sum_h w2*relu(ti+tj) = pi + pj + sum_h (w2/2)*|ti+tj| ; |.| = packed AND.
#define K4_IT 32
__global__ void __launch_bounds__(256) k4_score(
    const int* __restrict__ adj, const float* __restrict__ w2,
    const float* __restrict__ b2, float* __restrict__ out)
{
    __shared__ ull   ti_s[K4_IT*16];
    __shared__ float pi_s[K4_IT];
    __shared__ ull   w2p_s[16];
    int t = threadIdx.x, lane = t & 31, w = t >> 5;
    int b  = blockIdx.z;
    int i0 = blockIdx.y * K4_IT;
    int j  = blockIdx.x * 256 + w*32 + lane;

    const ull* tiu = (const ull*)ti_buf + ((size_t)(b*NNODE) + i0)*16;
    for (int idx = t; idx < K4_IT*16; idx += 256) ti_s[idx] = tiu[idx];
    if (t < K4_IT) pi_s[t] = pi_buf[(size_t)(b*NNODE) + i0 + t];
    if (t < 16)    w2p_s[t] = pack2(0.5f*w2[2*t], 0.5f*w2[2*t+1]);
    __syncthreads();

    ull tj2[16], w2r[16];
    const ull* tjp = (const ull*)tjT_buf;
#pragma unroll
    for (int p = 0; p < 16; ++p) tj2[p] = tjp[((size_t)b*16 + p)*NNODE + j];
#pragma unroll
    for (int p = 0; p < 16; ++p) w2r[p] = w2p_s[p];
    float pj  = pj_buf[(size_t)(b*NNODE) + j];
    float b2v = b2[0] + pj;

    const int* arow = adj + ((size_t)(b*NNODE) + i0)*NNODE + j;
    float*     orow = out + ((size_t)(b*NNODE) + i0)*NNODE + j;
    const ull ABS2 = 0x7FFFFFFF7FFFFFFFull;

    for (int i = 0; i < K4_IT; ++i) {
        const ulonglong2* tp = (const ulonglong2*)&ti_s[i*16];
        ull a0 = 0, a1 = 0, a2 = 0, a3 = 0;
#pragma unroll
        for (int q = 0; q < 8; ++q) {
            ulonglong2 tv = tp[q];                  // LDS.128 broadcast
            ull s0 = add2(tj2[2*q],   tv.x) & ABS2; // packed |ti+tj|
            ull s1 = add2(tj2[2*q+1], tv.y) & ABS2;
            if (q & 1) {
                a2 = fma2(w2r[2*q],   s0, a2);
                a3 = fma2(w2r[2*q+1], s1, a3);
            } else {
                a0 = fma2(w2r[2*q],   s0, a0);
                a1 = fma2(w2r[2*q+1], s1, a1);
            }
        }
        float2 s0 = unpack2(a0), s1 = unpack2(a1), s2 = unpack2(a2), s3 = unpack2(a3);
        float logit = ((s0.x + s0.y) + (s1.x + s1.y)) + ((s2.x + s2.y) + (s3.x + s3.y))
                    + pi_s[i] + b2v;
        float e  = ex2f(-1.4426950409f * logit);    // exp(-logit)
        float sc = __fdividef(1.f, 1.f + e);

        int ii = i0 + i;
        int av = arow[(size_t)i * NNODE];           // coalesced (lane = j)
        orow[(size_t)i * NNODE] = (av != 0 && ii != j) ? sc : 0.f;
    }
}

// ================= launch =================
extern "C" void kernel_launch(void* const* d_in, const int* in_sizes, int n_in,
                              void* d_out, int out_size)
{
    const float* x        = (const float*)d_in[0];
    const int*   adj      = (const int*)  d_in[1];
    const float* Wp       = (const float*)d_in[2];
    const float* bp       = (const float*)d_in[3];
    const float* Wg       = (const float*)d_in[4];
    const float* att_src  = (const float*)d_in[5];
    const float* att_dst  = (const float*)d_in[6];
    const float* bias_g   = (const float*)d_in[7];
    const float* W1       = (const float*)d_in[8];
    const float* b1       = (const float*)d_in[9];
    const float* w2       = (const float*)d_in[10];
    const float* b2       = (const float*)d_in[11];
    float* out = (float*)d_out;

    // one pad: shifts the ncu -s 5 capture slot onto k4 (diagnostic)
    pad_k<<<1, 32>>>();

    k1_embed<<<BB*NNODE/32, 128>>>(x, Wp, bp, Wg, att_src, att_dst);

    cudaFuncSetAttribute(k2_attn, cudaFuncAttributeMaxDynamicSharedMemorySize, SM_TOTAL);
    k2_attn<<<dim3(NNODE/32, BB), 512, SM_TOTAL>>>(adj, bias_g, W1, b1, w2);

    k4_score<<<dim3(2, NNODE/K4_IT, BB), 256>>>(adj, w2, b2, out);
}